// round 15
// baseline (speedup 1.0000x reference)
#include <cuda_runtime.h>
#include <cuda_bf16.h>
#include <cstdint>

// Problem constants
#define T_SEQ   2048
#define N_BATCH 4
#define C_DIM   768
#define N_HEADS 12
#define H_DIM   64
#define M_ROWS  (N_BATCH * T_SEQ)   // 8192

// ---------------------------------------------------------------------------
// Global scratch (static __device__ arrays; allocation-free per harness rules)
// ---------------------------------------------------------------------------
__device__ float g_qkv[(size_t)M_ROWS * 3 * C_DIM];
__device__ __align__(16) __nv_bfloat16 g_xhi[(size_t)M_ROWS * C_DIM];
__device__ __align__(16) __nv_bfloat16 g_xlo[(size_t)M_ROWS * C_DIM];
__device__ __align__(16) __nv_bfloat16 g_wqh[(size_t)3 * C_DIM * C_DIM];
__device__ __align__(16) __nv_bfloat16 g_wql[(size_t)3 * C_DIM * C_DIM];
__device__ __align__(16) __nv_bfloat16 g_wph[(size_t)C_DIM * C_DIM];
__device__ __align__(16) __nv_bfloat16 g_wpl[(size_t)C_DIM * C_DIM];
#define KVPLANE ((size_t)N_BATCH * N_HEADS * T_SEQ * H_DIM)
__device__ __align__(16) __nv_bfloat16 g_khi[KVPLANE];
__device__ __align__(16) __nv_bfloat16 g_klo[KVPLANE];
__device__ __align__(16) __nv_bfloat16 g_vhi[KVPLANE];
__device__ __align__(16) __nv_bfloat16 g_vlo[KVPLANE];
__device__ __align__(16) __nv_bfloat16 g_ahi[(size_t)M_ROWS * C_DIM];
__device__ __align__(16) __nv_bfloat16 g_alo[(size_t)M_ROWS * C_DIM];

// ===========================================================================
// helpers
// ===========================================================================
__device__ __forceinline__ uint32_t smem_u32(const void* p) {
    uint32_t a;
    asm("{ .reg .u64 t; cvta.to.shared.u64 t, %1; cvt.u32.u64 %0, t; }"
        : "=r"(a) : "l"(p));
    return a;
}

#define LDSM4(r, addr) \
    asm volatile("ldmatrix.sync.aligned.m8n8.x4.shared.b16 {%0,%1,%2,%3}, [%4];" \
                 : "=r"((r)[0]), "=r"((r)[1]), "=r"((r)[2]), "=r"((r)[3]) \
                 : "r"(addr))

#define LDSM4T(r, addr) \
    asm volatile("ldmatrix.sync.aligned.m8n8.x4.trans.shared.b16 {%0,%1,%2,%3}, [%4];" \
                 : "=r"((r)[0]), "=r"((r)[1]), "=r"((r)[2]), "=r"((r)[3]) \
                 : "r"(addr))

#define MMA_BF16(c, a, b) \
    asm volatile("mma.sync.aligned.m16n8k16.row.col.f32.bf16.bf16.f32 " \
                 "{%0,%1,%2,%3}, {%4,%5,%6,%7}, {%8,%9}, {%0,%1,%2,%3};" \
                 : "+f"((c)[0]), "+f"((c)[1]), "+f"((c)[2]), "+f"((c)[3]) \
                 : "r"((a)[0]), "r"((a)[1]), "r"((a)[2]), "r"((a)[3]), \
                   "r"((b)[0]), "r"((b)[1]))

#define CP16(sdst, gsrc) \
    asm volatile("cp.async.ca.shared.global [%0], [%1], 16;" \
                 :: "r"(sdst), "l"(gsrc) : "memory")
#define CP_COMMIT() asm volatile("cp.async.commit_group;" ::: "memory")
#define CP_WAIT0()  asm volatile("cp.async.wait_group 0;" ::: "memory")
#define CP_WAIT1()  asm volatile("cp.async.wait_group 1;" ::: "memory")

__device__ __forceinline__ void split2(float x, float y, uint32_t& hi, uint32_t& lo) {
    __nv_bfloat16 hx = __float2bfloat16_rn(x);
    __nv_bfloat16 hy = __float2bfloat16_rn(y);
    float lx = x - __bfloat162float(hx);
    float ly = y - __bfloat162float(hy);
    __nv_bfloat16 lxh = __float2bfloat16_rn(lx);
    __nv_bfloat16 lyh = __float2bfloat16_rn(ly);
    hi = (uint32_t)__bfloat16_as_ushort(hx) | ((uint32_t)__bfloat16_as_ushort(hy) << 16);
    lo = (uint32_t)__bfloat16_as_ushort(lxh) | ((uint32_t)__bfloat16_as_ushort(lyh) << 16);
}

// Fast 2^t on the FMA pipe (t <= 0 in softmax use). rel err ~3e-6.
__device__ __forceinline__ float exp2_fast(float t) {
    t = fmaxf(t, -100.0f);
    float n = rintf(t);
    float f = t - n;
    float u = f * 0.6931471805599453f;
    float r = 8.3333333e-3f;
    r = fmaf(r, u, 4.1666667e-2f);
    r = fmaf(r, u, 1.6666667e-1f);
    r = fmaf(r, u, 5.0e-1f);
    r = fmaf(r, u, 1.0f);
    r = fmaf(r, u, 1.0f);
    int e = (int)n;
    return r * __int_as_float((e + 127) << 23);
}

// ===========================================================================
// Prep: ONE kernel splits all three f32 inputs into bf16 hi/lo planes.
// ===========================================================================
#define N4_X  (M_ROWS * C_DIM / 4)
#define N4_WQ (3 * C_DIM * C_DIM / 4)
#define N4_WP (C_DIM * C_DIM / 4)
#define N4_TOTAL (N4_X + N4_WQ + N4_WP)

__global__ void split_all_kernel(const float4* __restrict__ x,
                                 const float4* __restrict__ wq,
                                 const float4* __restrict__ wp)
{
    int i = blockIdx.x * blockDim.x + threadIdx.x;
    if (i >= N4_TOTAL) return;
    const float4* src;
    uint2 *hi, *lo;
    int j;
    if (i < N4_X) {
        src = x;  j = i;
        hi = (uint2*)g_xhi; lo = (uint2*)g_xlo;
    } else if (i < N4_X + N4_WQ) {
        src = wq; j = i - N4_X;
        hi = (uint2*)g_wqh; lo = (uint2*)g_wql;
    } else {
        src = wp; j = i - N4_X - N4_WQ;
        hi = (uint2*)g_wph; lo = (uint2*)g_wpl;
    }
    float4 v = src[j];
    uint32_t h0, l0, h1, l1;
    split2(v.x, v.y, h0, l0);
    split2(v.z, v.w, h1, l1);
    hi[j] = make_uint2(h0, h1);
    lo[j] = make_uint2(l0, l1);
}

// split K,V sections of g_qkv into per-(b,h) planes [B,H,T,64]
__global__ void split_kv_kernel(const float* __restrict__ qkv)
{
    int i4 = blockIdx.x * blockDim.x + threadIdx.x;
    const int total = N_BATCH * T_SEQ * C_DIM / 4;
    if (i4 >= total) return;
    int flat = i4 * 4;
    int b = flat / (T_SEQ * C_DIM);
    int rem = flat - b * (T_SEQ * C_DIM);
    int t = rem / C_DIM;
    int c = rem - t * C_DIM;
    int h = c >> 6, d = c & 63;
    size_t src = (size_t)(b * T_SEQ + t) * (3 * C_DIM);
    size_t dst = ((size_t)(b * N_HEADS + h) * T_SEQ + t) * H_DIM + d;
    float4 kv = *(const float4*)(qkv + src + C_DIM + c);
    float4 vv = *(const float4*)(qkv + src + 2 * C_DIM + c);
    uint32_t h0, l0, h1, l1;
    split2(kv.x, kv.y, h0, l0); split2(kv.z, kv.w, h1, l1);
    *(uint2*)(g_khi + dst) = make_uint2(h0, h1);
    *(uint2*)(g_klo + dst) = make_uint2(l0, l1);
    split2(vv.x, vv.y, h0, l0); split2(vv.z, vv.w, h1, l1);
    *(uint2*)(g_vhi + dst) = make_uint2(h0, h1);
    *(uint2*)(g_vlo + dst) = make_uint2(l0, l1);
}

// ===========================================================================
// bf16x3 GEMM on pre-split planes (round-13 verified form).
// 256-thread CTA, block 128x256, BK=32, 8 warps, warp tile 64x64,
// 3-stage cp.async, accumulator-major MMA order.
// ===========================================================================
#define SROW 40
#define GA_B (128 * SROW * 2)
#define GB_B (256 * SROW * 2)
#define G_STGB (2 * GA_B + 2 * GB_B)
#define GEMM_DSMEM (3 * G_STGB)

__global__ __launch_bounds__(256, 1)
void gemm_planes(const __nv_bfloat16* __restrict__ Ahi,
                 const __nv_bfloat16* __restrict__ Alo,
                 const __nv_bfloat16* __restrict__ Bhi,
                 const __nv_bfloat16* __restrict__ Blo,
                 const float* __restrict__ bias,
                 float* __restrict__ C,
                 int Nd, int Kd)
{
    extern __shared__ __align__(16) char dsmg[];
    const uint32_t sb = smem_u32(dsmg);

    const int tid  = threadIdx.x;
    const int lane = tid & 31;
    const int wid  = tid >> 5;
    const int wm   = wid & 1;
    const int wn   = wid >> 1;
    const int bn = blockIdx.x, bm = blockIdx.y;

    const int paP = tid >> 7, paR = tid & 127;
    const char* gA = (const char*)((paP ? Alo : Ahi) + (size_t)(bm * 128 + paR) * Kd);
    const uint32_t sA = sb + (uint32_t)paP * GA_B + (uint32_t)paR * 80u;
    const int pbP = tid >> 7, pbR = (tid & 127) * 2;
    const char* gB = (const char*)((pbP ? Blo : Bhi) + (size_t)(bn * 256 + pbR) * Kd);
    const uint32_t sB = sb + 2u * GA_B + (uint32_t)pbP * GB_B + (uint32_t)pbR * 80u;

    float acc[4][8][4];
    #pragma unroll
    for (int mt = 0; mt < 4; mt++)
        #pragma unroll
        for (int nt = 0; nt < 8; nt++)
            #pragma unroll
            for (int q = 0; q < 4; q++) acc[mt][nt][q] = 0.0f;

    const uint32_t aOff = ((uint32_t)(wm * 64 + (lane & 15)) * SROW + (lane >> 4) * 8) * 2;
    const uint32_t bOff = ((uint32_t)(wn * 64 + ((lane >> 4) & 1) * 8 + (lane & 7)) * SROW
                          + ((lane >> 3) & 1) * 8) * 2;
    const uint32_t aHiB = sb + aOff;
    const uint32_t aLoB = sb + GA_B + aOff;
    const uint32_t bHiB = sb + 2 * GA_B + bOff;
    const uint32_t bLoB = sb + 2 * GA_B + GB_B + bOff;

    const int nch = Kd / 32;

    {
        #pragma unroll
        for (int c = 0; c < 4; c++) CP16(sA + c * 16, gA + c * 16);
        #pragma unroll
        for (int c = 0; c < 4; c++) {
            CP16(sB + c * 16,      gB + c * 16);
            CP16(sB + 80 + c * 16, gB + (size_t)Kd * 2 + c * 16);
        }
        CP_COMMIT();
    }

    for (int ch = 0; ch < nch; ch++) {
        if (ch + 1 < nch) {
            const uint32_t sw = (uint32_t)((ch + 1) % 3) * G_STGB;
            const int gb = (ch + 1) * 64;
            #pragma unroll
            for (int c = 0; c < 4; c++) CP16(sA + sw + c * 16, gA + gb + c * 16);
            #pragma unroll
            for (int c = 0; c < 4; c++) {
                CP16(sB + sw + c * 16,      gB + gb + c * 16);
                CP16(sB + sw + 80 + c * 16, gB + (size_t)Kd * 2 + gb + c * 16);
            }
            CP_COMMIT();
            CP_WAIT1();
        } else {
            CP_WAIT0();
        }
        __syncthreads();

        const uint32_t so = (uint32_t)(ch % 3) * G_STGB;
        #pragma unroll
        for (int ks = 0; ks < 2; ks++) {
            uint32_t ah[4][4], al[4][4], bh[8][2], bl[8][2];
            #pragma unroll
            for (int mt = 0; mt < 4; mt++) {
                const uint32_t ad = (uint32_t)(mt * 16 * SROW + ks * 16) * 2 + so;
                LDSM4(ah[mt], aHiB + ad);
                LDSM4(al[mt], aLoB + ad);
            }
            #pragma unroll
            for (int p4 = 0; p4 < 4; p4++) {
                const uint32_t bd = (uint32_t)(p4 * 16 * SROW + ks * 16) * 2 + so;
                uint32_t r[4];
                LDSM4(r, bHiB + bd);
                bh[2*p4][0] = r[0]; bh[2*p4][1] = r[1];
                bh[2*p4+1][0] = r[2]; bh[2*p4+1][1] = r[3];
                LDSM4(r, bLoB + bd);
                bl[2*p4][0] = r[0]; bl[2*p4][1] = r[1];
                bl[2*p4+1][0] = r[2]; bl[2*p4+1][1] = r[3];
            }
            #pragma unroll
            for (int mt = 0; mt < 4; mt++)
                #pragma unroll
                for (int nt = 0; nt < 8; nt++) {
                    MMA_BF16(acc[mt][nt], ah[mt], bh[nt]);
                    MMA_BF16(acc[mt][nt], al[mt], bh[nt]);
                    MMA_BF16(acc[mt][nt], ah[mt], bl[nt]);
                }
        }
    }

    const int gid = lane >> 2, tig = lane & 3;
    const int row0 = bm * 128 + wm * 64;
    const int col0 = bn * 256 + wn * 64;
    #pragma unroll
    for (int mt = 0; mt < 4; mt++)
        #pragma unroll
        for (int nt = 0; nt < 8; nt++) {
            const int r  = row0 + mt * 16 + gid;
            const int cc = col0 + nt * 8 + tig * 2;
            const float2 bz = *(const float2*)(bias + cc);
            float2 o0, o1;
            o0.x = acc[mt][nt][0] + bz.x; o0.y = acc[mt][nt][1] + bz.y;
            o1.x = acc[mt][nt][2] + bz.x; o1.y = acc[mt][nt][3] + bz.y;
            *(float2*)(C + (size_t)r * Nd + cc)       = o0;
            *(float2*)(C + (size_t)(r + 8) * Nd + cc) = o1;
        }
}

// ===========================================================================
// MMA flash attention. 256-thread CTA = 256 q-rows x 1 head, 8 warps x
// 32 q-rows. 128-KEY smem stages (2 stages), computed as two 64-key
// sub-blocks; warps 0-3 process subs in order (0,1), warps 4-7 in (1,0)
// -> softmax of one warp-group overlaps MMAs of the other. Online-softmax
// merge is order-commutative, so results are valid.
// ===========================================================================
#define NKROW 36                           // u32 per smem row
#define A2U   (128 * NKROW)                // u32 per 128x64 array (4608)
#define A2B   (A2U * 4)                    // 18432 bytes
#define SUBB  (64 * NKROW * 4)             // 9216 bytes per 64-key sub-block
#define STG2_U32 (4 * A2U)                 // Khi,Klo,Vhi,Vlo (18432 u32)
#define STG2_B   (STG2_U32 * 4)            // 73728 bytes
#define ATTN_DSMEM (2 * STG2_B)            // 147456
#define QSCALE 11.541560327111707f

__global__ __launch_bounds__(256, 1)
void attn_mma(const float* __restrict__ qkv)
{
    extern __shared__ __align__(16) uint32_t dsm[];

    const int tid  = threadIdx.x;
    const int lane = tid & 31;
    const int w    = tid >> 5;
    const int g    = lane >> 2;
    const int tig  = lane & 3;
    const int m0   = blockIdx.x * 256;
    const int h    = blockIdx.y;
    const int b    = blockIdx.z;

    const float* base = qkv + (size_t)b * T_SEQ * (3*C_DIM) + h * H_DIM;
    const uint32_t sb = smem_u32(dsm);

    // ---- K/V producer: plane pp = tid>>6, rows rr and rr+64 ----
    const int pp = tid >> 6;
    const int rr = tid & 63;
    const __nv_bfloat16* kvpl = (pp == 0) ? g_khi : (pp == 1) ? g_klo
                               : (pp == 2) ? g_vhi : g_vlo;
    const char* gsrc0 = (const char*)(kvpl + ((size_t)(b * N_HEADS + h) * T_SEQ + rr) * H_DIM);
    const uint32_t sdst0 = sb + (uint32_t)pp * A2B + (uint32_t)rr * 144;

    // prologue: key-block 0 (128 keys) -> stage 0
    {
        #pragma unroll
        for (int c = 0; c < 8; c++) {
            CP16(sdst0 + c * 16,        gsrc0 + c * 16);
            CP16(sdst0 + 9216 + c * 16, gsrc0 + 8192 + c * 16);   // row rr+64
        }
        CP_COMMIT();
    }
    // Q (scaled+split): 256 rows -> stage 1 (hi at +0, lo at +SUBB*4... lo at half)
    {
        const int r = tid;
        const float* qrow = base + (size_t)(m0 + r) * (3*C_DIM);
        uint32_t* dhi = dsm + STG2_U32 + r * NKROW;             // stage1 first half
        uint32_t* dlo = dsm + STG2_U32 + 9216 + r * NKROW;      // stage1 second half
        #pragma unroll
        for (int i = 0; i < 16; i++) {
            float4 v = *(const float4*)(qrow + i * 4);
            uint32_t h0, l0, h1, l1;
            split2(v.x * QSCALE, v.y * QSCALE, h0, l0);
            split2(v.z * QSCALE, v.w * QSCALE, h1, l1);
            dhi[i*2] = h0; dhi[i*2+1] = h1;
            dlo[i*2] = l0; dlo[i*2+1] = l1;
        }
    }
    __syncthreads();

    uint32_t qh[2][4][4], ql[2][4][4];
    const int t = lane >> 3, rl = lane & 7;
    {
        #pragma unroll
        for (int mt2 = 0; mt2 < 2; mt2++)
            #pragma unroll
            for (int ks = 0; ks < 4; ks++) {
                const uint32_t off =
                    ((uint32_t)(w * 32 + mt2 * 16 + (t & 1) * 8 + rl) * NKROW
                     + ks * 8 + (t >> 1) * 4) * 4;
                LDSM4(qh[mt2][ks], sb + STG2_B + off);
                LDSM4(ql[mt2][ks], sb + STG2_B + 36864 + off);
            }
    }
    __syncthreads();   // Q in registers; stage 1 free

    float o[2][8][4];
    #pragma unroll
    for (int mt2 = 0; mt2 < 2; mt2++)
        #pragma unroll
        for (int nt = 0; nt < 8; nt++)
            #pragma unroll
            for (int j = 0; j < 4; j++) o[mt2][nt][j] = 0.0f;
    float m_[2][2] = {{-1e30f, -1e30f}, {-1e30f, -1e30f}};
    float l_[2][2] = {{0.0f, 0.0f}, {0.0f, 0.0f}};

    const int subXor = (w >> 2) & 1;   // warps 4-7 process sub-blocks in reverse

    constexpr int NT2 = T_SEQ / 128;   // 16 key-blocks
    for (int kt = 0; kt < NT2; kt++) {
        CP_WAIT0();          // key-block kt arrived
        __syncthreads();     // all warps done reading the other stage
        if (kt + 1 < NT2) {  // issue block kt+1 -> other stage (overlaps compute)
            const uint32_t sw = (uint32_t)((kt + 1) & 1) * STG2_B;
            const char* gs = gsrc0 + (size_t)(kt + 1) * 128 * H_DIM * 2;
            #pragma unroll
            for (int c = 0; c < 8; c++) {
                CP16(sdst0 + sw + c * 16,        gs + c * 16);
                CP16(sdst0 + sw + 9216 + c * 16, gs + 8192 + c * 16);
            }
            CP_COMMIT();
        }

        const uint32_t so = (uint32_t)(kt & 1) * STG2_B;

        #pragma unroll
        for (int ss = 0; ss < 2; ss++) {
            const int sub = ss ^ subXor;
            const uint32_t soS = so + (uint32_t)sub * SUBB;

            // ---- S = Q K^T (bf16x3) over this 64-key sub-block ----
            float s[2][8][4];
            #pragma unroll
            for (int mt2 = 0; mt2 < 2; mt2++)
                #pragma unroll
                for (int nt = 0; nt < 8; nt++)
                    #pragma unroll
                    for (int j = 0; j < 4; j++) s[mt2][nt][j] = 0.0f;

            #pragma unroll
            for (int ks = 0; ks < 4; ks++) {
                #pragma unroll
                for (int kb = 0; kb < 4; kb++) {
                    const uint32_t off = soS +
                        ((uint32_t)(kb * 16 + (t >> 1) * 8 + rl) * NKROW + ks * 8 + (t & 1) * 4) * 4;
                    uint32_t rh[4], rlo[4];
                    LDSM4(rh, sb + off);
                    LDSM4(rlo, sb + A2B + off);
                    #pragma unroll
                    for (int mt2 = 0; mt2 < 2; mt2++) {
                        MMA_BF16(s[mt2][2*kb],   qh[mt2][ks], rh);
                        MMA_BF16(s[mt2][2*kb],   ql[mt2][ks], rh);
                        MMA_BF16(s[mt2][2*kb],   qh[mt2][ks], rlo);
                        MMA_BF16(s[mt2][2*kb+1], qh[mt2][ks], rh + 2);
                        MMA_BF16(s[mt2][2*kb+1], ql[mt2][ks], rh + 2);
                        MMA_BF16(s[mt2][2*kb+1], qh[mt2][ks], rlo + 2);
                    }
                }
            }

            // ---- online softmax per m-tile ----
            #pragma unroll
            for (int mt2 = 0; mt2 < 2; mt2++) {
                float rm0 = -1e30f, rm1 = -1e30f;
                #pragma unroll
                for (int nt = 0; nt < 8; nt++) {
                    rm0 = fmaxf(rm0, fmaxf(s[mt2][nt][0], s[mt2][nt][1]));
                    rm1 = fmaxf(rm1, fmaxf(s[mt2][nt][2], s[mt2][nt][3]));
                }
                rm0 = fmaxf(rm0, __shfl_xor_sync(0xffffffffu, rm0, 1));
                rm0 = fmaxf(rm0, __shfl_xor_sync(0xffffffffu, rm0, 2));
                rm1 = fmaxf(rm1, __shfl_xor_sync(0xffffffffu, rm1, 1));
                rm1 = fmaxf(rm1, __shfl_xor_sync(0xffffffffu, rm1, 2));
                const float mn0 = fmaxf(m_[mt2][0], rm0);
                const float mn1 = fmaxf(m_[mt2][1], rm1);
                const float sc0 = exp2_fast(m_[mt2][0] - mn0);
                const float sc1 = exp2_fast(m_[mt2][1] - mn1);
                m_[mt2][0] = mn0; m_[mt2][1] = mn1;

                float rs0 = 0.0f, rs1 = 0.0f;
                #pragma unroll
                for (int nt = 0; nt < 8; nt++) {
                    s[mt2][nt][0] = exp2_fast(s[mt2][nt][0] - mn0);
                    s[mt2][nt][1] = exp2_fast(s[mt2][nt][1] - mn0);
                    s[mt2][nt][2] = exp2_fast(s[mt2][nt][2] - mn1);
                    s[mt2][nt][3] = exp2_fast(s[mt2][nt][3] - mn1);
                    rs0 += s[mt2][nt][0] + s[mt2][nt][1];
                    rs1 += s[mt2][nt][2] + s[mt2][nt][3];
                }
                rs0 += __shfl_xor_sync(0xffffffffu, rs0, 1);
                rs0 += __shfl_xor_sync(0xffffffffu, rs0, 2);
                rs1 += __shfl_xor_sync(0xffffffffu, rs1, 1);
                rs1 += __shfl_xor_sync(0xffffffffu, rs1, 2);
                l_[mt2][0] = l_[mt2][0] * sc0 + rs0;
                l_[mt2][1] = l_[mt2][1] * sc1 + rs1;

                #pragma unroll
                for (int nt = 0; nt < 8; nt++) {
                    o[mt2][nt][0] *= sc0; o[mt2][nt][1] *= sc0;
                    o[mt2][nt][2] *= sc1; o[mt2][nt][3] *= sc1;
                }
            }

            // ---- O += P V (bf16x3) over this sub-block ----
            #pragma unroll
            for (int ks2 = 0; ks2 < 4; ks2++) {
                uint32_t pah[2][4], pal[2][4];
                #pragma unroll
                for (int mt2 = 0; mt2 < 2; mt2++) {
                    split2(s[mt2][2*ks2][0],   s[mt2][2*ks2][1],   pah[mt2][0], pal[mt2][0]);
                    split2(s[mt2][2*ks2][2],   s[mt2][2*ks2][3],   pah[mt2][1], pal[mt2][1]);
                    split2(s[mt2][2*ks2+1][0], s[mt2][2*ks2+1][1], pah[mt2][2], pal[mt2][2]);
                    split2(s[mt2][2*ks2+1][2], s[mt2][2*ks2+1][3], pah[mt2][3], pal[mt2][3]);
                }
                #pragma unroll
                for (int db = 0; db < 4; db++) {
                    const uint32_t off = soS +
                        ((uint32_t)(ks2 * 16 + (t & 1) * 8 + rl) * NKROW + db * 8 + (t >> 1) * 4) * 4;
                    uint32_t rvh[4], rvl[4];
                    LDSM4T(rvh, sb + 2 * A2B + off);
                    LDSM4T(rvl, sb + 3 * A2B + off);
                    #pragma unroll
                    for (int mt2 = 0; mt2 < 2; mt2++) {
                        MMA_BF16(o[mt2][2*db],   pah[mt2], rvh);
                        MMA_BF16(o[mt2][2*db],   pal[mt2], rvh);
                        MMA_BF16(o[mt2][2*db],   pah[mt2], rvl);
                        MMA_BF16(o[mt2][2*db+1], pah[mt2], rvh + 2);
                        MMA_BF16(o[mt2][2*db+1], pal[mt2], rvh + 2);
                        MMA_BF16(o[mt2][2*db+1], pah[mt2], rvl + 2);
                    }
                }
            }
        }
    }

    // ---- epilogue: O / l -> bf16 hi/lo planes for the proj GEMM ----
    #pragma unroll
    for (int mt2 = 0; mt2 < 2; mt2++) {
        const float inv0 = 1.0f / l_[mt2][0];
        const float inv1 = 1.0f / l_[mt2][1];
        const int qrow = m0 + w * 32 + mt2 * 16 + g;
        const size_t off0 = (size_t)(b * T_SEQ + qrow) * C_DIM + h * H_DIM;
        const size_t off1 = off0 + (size_t)8 * C_DIM;
        #pragma unroll
        for (int nt = 0; nt < 8; nt++) {
            uint32_t hh, ll;
            split2(o[mt2][nt][0] * inv0, o[mt2][nt][1] * inv0, hh, ll);
            *(uint32_t*)(g_ahi + off0 + nt * 8 + tig * 2) = hh;
            *(uint32_t*)(g_alo + off0 + nt * 8 + tig * 2) = ll;
            split2(o[mt2][nt][2] * inv1, o[mt2][nt][3] * inv1, hh, ll);
            *(uint32_t*)(g_ahi + off1 + nt * 8 + tig * 2) = hh;
            *(uint32_t*)(g_alo + off1 + nt * 8 + tig * 2) = ll;
        }
    }
}

// ===========================================================================
extern "C" void kernel_launch(void* const* d_in, const int* in_sizes, int n_in,
                              void* d_out, int out_size)
{
    (void)in_sizes; (void)n_in; (void)out_size;
    const float* x      = (const float*)d_in[0];
    const float* qkv_w  = (const float*)d_in[1];
    const float* qkv_b  = (const float*)d_in[2];
    const float* proj_w = (const float*)d_in[3];
    const float* proj_b = (const float*)d_in[4];
    float* out = (float*)d_out;

    float* qkv_ptr;
    cudaGetSymbolAddress((void**)&qkv_ptr, g_qkv);
    __nv_bfloat16 *xhi, *xlo, *wqh, *wql, *wph, *wpl, *ahi, *alo;
    cudaGetSymbolAddress((void**)&xhi, g_xhi);
    cudaGetSymbolAddress((void**)&xlo, g_xlo);
    cudaGetSymbolAddress((void**)&wqh, g_wqh);
    cudaGetSymbolAddress((void**)&wql, g_wql);
    cudaGetSymbolAddress((void**)&wph, g_wph);
    cudaGetSymbolAddress((void**)&wpl, g_wpl);
    cudaGetSymbolAddress((void**)&ahi, g_ahi);
    cudaGetSymbolAddress((void**)&alo, g_alo);

    cudaFuncSetAttribute(gemm_planes, cudaFuncAttributeMaxDynamicSharedMemorySize, GEMM_DSMEM);
    cudaFuncSetAttribute(attn_mma, cudaFuncAttributeMaxDynamicSharedMemorySize, ATTN_DSMEM);

    // 0) ONE fused prep kernel: split x, qkv_w, proj_w into bf16 hi/lo planes
    split_all_kernel<<<(N4_TOTAL + 255) / 256, 256>>>(
        (const float4*)x, (const float4*)qkv_w, (const float4*)proj_w);

    // 1) QKV GEMM: planes -> g_qkv (f32)
    gemm_planes<<<dim3(3*C_DIM/256, M_ROWS/128), 256, GEMM_DSMEM>>>(
        xhi, xlo, wqh, wql, qkv_b, qkv_ptr, 3*C_DIM, C_DIM);

    // 2) split K/V once into per-(b,h) bf16 planes
    {
        const int n4 = N_BATCH * T_SEQ * C_DIM / 4;
        split_kv_kernel<<<(n4 + 255) / 256, 256>>>(qkv_ptr);
    }

    // 3) MMA flash attention (128-key stages, staggered sub-blocks)
    attn_mma<<<dim3(T_SEQ/256, N_HEADS, N_BATCH), 256, ATTN_DSMEM>>>(qkv_ptr);

    // 4) proj GEMM: planes -> out (f32)
    gemm_planes<<<dim3(C_DIM/256, M_ROWS/128), 256, GEMM_DSMEM>>>(
        ahi, alo, wph, wpl, proj_b, out, C_DIM, C_DIM);
}

// round 16
// speedup vs baseline: 1.0268x; 1.0268x over previous
#include <cuda_runtime.h>
#include <cuda_bf16.h>
#include <cstdint>

// Problem constants
#define T_SEQ   2048
#define N_BATCH 4
#define C_DIM   768
#define N_HEADS 12
#define H_DIM   64
#define M_ROWS  (N_BATCH * T_SEQ)   // 8192

// ---------------------------------------------------------------------------
// Global scratch (static __device__ arrays; allocation-free per harness rules)
// ---------------------------------------------------------------------------
__device__ float g_qkv[(size_t)M_ROWS * 3 * C_DIM];
__device__ __align__(16) __nv_bfloat16 g_xhi[(size_t)M_ROWS * C_DIM];
__device__ __align__(16) __nv_bfloat16 g_xlo[(size_t)M_ROWS * C_DIM];
__device__ __align__(16) __nv_bfloat16 g_wqh[(size_t)3 * C_DIM * C_DIM];
__device__ __align__(16) __nv_bfloat16 g_wql[(size_t)3 * C_DIM * C_DIM];
__device__ __align__(16) __nv_bfloat16 g_wph[(size_t)C_DIM * C_DIM];
__device__ __align__(16) __nv_bfloat16 g_wpl[(size_t)C_DIM * C_DIM];
#define KVPLANE ((size_t)N_BATCH * N_HEADS * T_SEQ * H_DIM)
__device__ __align__(16) __nv_bfloat16 g_khi[KVPLANE];
__device__ __align__(16) __nv_bfloat16 g_klo[KVPLANE];
__device__ __align__(16) __nv_bfloat16 g_vhi[KVPLANE];
__device__ __align__(16) __nv_bfloat16 g_vlo[KVPLANE];
__device__ __align__(16) __nv_bfloat16 g_ahi[(size_t)M_ROWS * C_DIM];
__device__ __align__(16) __nv_bfloat16 g_alo[(size_t)M_ROWS * C_DIM];

// ===========================================================================
// helpers
// ===========================================================================
__device__ __forceinline__ uint32_t smem_u32(const void* p) {
    uint32_t a;
    asm("{ .reg .u64 t; cvta.to.shared.u64 t, %1; cvt.u32.u64 %0, t; }"
        : "=r"(a) : "l"(p));
    return a;
}

#define LDSM4(r, addr) \
    asm volatile("ldmatrix.sync.aligned.m8n8.x4.shared.b16 {%0,%1,%2,%3}, [%4];" \
                 : "=r"((r)[0]), "=r"((r)[1]), "=r"((r)[2]), "=r"((r)[3]) \
                 : "r"(addr))

#define LDSM4T(r, addr) \
    asm volatile("ldmatrix.sync.aligned.m8n8.x4.trans.shared.b16 {%0,%1,%2,%3}, [%4];" \
                 : "=r"((r)[0]), "=r"((r)[1]), "=r"((r)[2]), "=r"((r)[3]) \
                 : "r"(addr))

#define MMA_BF16(c, a, b) \
    asm volatile("mma.sync.aligned.m16n8k16.row.col.f32.bf16.bf16.f32 " \
                 "{%0,%1,%2,%3}, {%4,%5,%6,%7}, {%8,%9}, {%0,%1,%2,%3};" \
                 : "+f"((c)[0]), "+f"((c)[1]), "+f"((c)[2]), "+f"((c)[3]) \
                 : "r"((a)[0]), "r"((a)[1]), "r"((a)[2]), "r"((a)[3]), \
                   "r"((b)[0]), "r"((b)[1]))

#define CP16(sdst, gsrc) \
    asm volatile("cp.async.ca.shared.global [%0], [%1], 16;" \
                 :: "r"(sdst), "l"(gsrc) : "memory")
#define CP_COMMIT() asm volatile("cp.async.commit_group;" ::: "memory")
#define CP_WAIT0()  asm volatile("cp.async.wait_group 0;" ::: "memory")
#define CP_WAIT1()  asm volatile("cp.async.wait_group 1;" ::: "memory")

__device__ __forceinline__ void split2(float x, float y, uint32_t& hi, uint32_t& lo) {
    __nv_bfloat16 hx = __float2bfloat16_rn(x);
    __nv_bfloat16 hy = __float2bfloat16_rn(y);
    float lx = x - __bfloat162float(hx);
    float ly = y - __bfloat162float(hy);
    __nv_bfloat16 lxh = __float2bfloat16_rn(lx);
    __nv_bfloat16 lyh = __float2bfloat16_rn(ly);
    hi = (uint32_t)__bfloat16_as_ushort(hx) | ((uint32_t)__bfloat16_as_ushort(hy) << 16);
    lo = (uint32_t)__bfloat16_as_ushort(lxh) | ((uint32_t)__bfloat16_as_ushort(lyh) << 16);
}

// Fast 2^t on the FMA pipe (t <= 0 in softmax use). rel err ~3e-6.
__device__ __forceinline__ float exp2_fast(float t) {
    t = fmaxf(t, -100.0f);
    float n = rintf(t);
    float f = t - n;
    float u = f * 0.6931471805599453f;
    float r = 8.3333333e-3f;
    r = fmaf(r, u, 4.1666667e-2f);
    r = fmaf(r, u, 1.6666667e-1f);
    r = fmaf(r, u, 5.0e-1f);
    r = fmaf(r, u, 1.0f);
    r = fmaf(r, u, 1.0f);
    int e = (int)n;
    return r * __int_as_float((e + 127) << 23);
}

// ===========================================================================
// Prep: ONE kernel splits all three f32 inputs into bf16 hi/lo planes.
// ===========================================================================
#define N4_X  (M_ROWS * C_DIM / 4)
#define N4_WQ (3 * C_DIM * C_DIM / 4)
#define N4_WP (C_DIM * C_DIM / 4)
#define N4_TOTAL (N4_X + N4_WQ + N4_WP)

__global__ void split_all_kernel(const float4* __restrict__ x,
                                 const float4* __restrict__ wq,
                                 const float4* __restrict__ wp)
{
    int i = blockIdx.x * blockDim.x + threadIdx.x;
    if (i >= N4_TOTAL) return;
    const float4* src;
    uint2 *hi, *lo;
    int j;
    if (i < N4_X) {
        src = x;  j = i;
        hi = (uint2*)g_xhi; lo = (uint2*)g_xlo;
    } else if (i < N4_X + N4_WQ) {
        src = wq; j = i - N4_X;
        hi = (uint2*)g_wqh; lo = (uint2*)g_wql;
    } else {
        src = wp; j = i - N4_X - N4_WQ;
        hi = (uint2*)g_wph; lo = (uint2*)g_wpl;
    }
    float4 v = src[j];
    uint32_t h0, l0, h1, l1;
    split2(v.x, v.y, h0, l0);
    split2(v.z, v.w, h1, l1);
    hi[j] = make_uint2(h0, h1);
    lo[j] = make_uint2(l0, l1);
}

// split K,V sections of g_qkv into per-(b,h) planes [B,H,T,64]
__global__ void split_kv_kernel(const float* __restrict__ qkv)
{
    int i4 = blockIdx.x * blockDim.x + threadIdx.x;
    const int total = N_BATCH * T_SEQ * C_DIM / 4;
    if (i4 >= total) return;
    int flat = i4 * 4;
    int b = flat / (T_SEQ * C_DIM);
    int rem = flat - b * (T_SEQ * C_DIM);
    int t = rem / C_DIM;
    int c = rem - t * C_DIM;
    int h = c >> 6, d = c & 63;
    size_t src = (size_t)(b * T_SEQ + t) * (3 * C_DIM);
    size_t dst = ((size_t)(b * N_HEADS + h) * T_SEQ + t) * H_DIM + d;
    float4 kv = *(const float4*)(qkv + src + C_DIM + c);
    float4 vv = *(const float4*)(qkv + src + 2 * C_DIM + c);
    uint32_t h0, l0, h1, l1;
    split2(kv.x, kv.y, h0, l0); split2(kv.z, kv.w, h1, l1);
    *(uint2*)(g_khi + dst) = make_uint2(h0, h1);
    *(uint2*)(g_klo + dst) = make_uint2(l0, l1);
    split2(vv.x, vv.y, h0, l0); split2(vv.z, vv.w, h1, l1);
    *(uint2*)(g_vhi + dst) = make_uint2(h0, h1);
    *(uint2*)(g_vlo + dst) = make_uint2(l0, l1);
}

// ===========================================================================
// bf16x3 GEMM on pre-split planes (round-13 verified form).
// 256-thread CTA, block 128x256, BK=32, 8 warps, warp tile 64x64,
// 3-stage cp.async, accumulator-major MMA order.
// ===========================================================================
#define SROW 40
#define GA_B (128 * SROW * 2)
#define GB_B (256 * SROW * 2)
#define G_STGB (2 * GA_B + 2 * GB_B)
#define GEMM_DSMEM (3 * G_STGB)

__global__ __launch_bounds__(256, 1)
void gemm_planes(const __nv_bfloat16* __restrict__ Ahi,
                 const __nv_bfloat16* __restrict__ Alo,
                 const __nv_bfloat16* __restrict__ Bhi,
                 const __nv_bfloat16* __restrict__ Blo,
                 const float* __restrict__ bias,
                 float* __restrict__ C,
                 int Nd, int Kd)
{
    extern __shared__ __align__(16) char dsmg[];
    const uint32_t sb = smem_u32(dsmg);

    const int tid  = threadIdx.x;
    const int lane = tid & 31;
    const int wid  = tid >> 5;
    const int wm   = wid & 1;
    const int wn   = wid >> 1;
    const int bn = blockIdx.x, bm = blockIdx.y;

    const int paP = tid >> 7, paR = tid & 127;
    const char* gA = (const char*)((paP ? Alo : Ahi) + (size_t)(bm * 128 + paR) * Kd);
    const uint32_t sA = sb + (uint32_t)paP * GA_B + (uint32_t)paR * 80u;
    const int pbP = tid >> 7, pbR = (tid & 127) * 2;
    const char* gB = (const char*)((pbP ? Blo : Bhi) + (size_t)(bn * 256 + pbR) * Kd);
    const uint32_t sB = sb + 2u * GA_B + (uint32_t)pbP * GB_B + (uint32_t)pbR * 80u;

    float acc[4][8][4];
    #pragma unroll
    for (int mt = 0; mt < 4; mt++)
        #pragma unroll
        for (int nt = 0; nt < 8; nt++)
            #pragma unroll
            for (int q = 0; q < 4; q++) acc[mt][nt][q] = 0.0f;

    const uint32_t aOff = ((uint32_t)(wm * 64 + (lane & 15)) * SROW + (lane >> 4) * 8) * 2;
    const uint32_t bOff = ((uint32_t)(wn * 64 + ((lane >> 4) & 1) * 8 + (lane & 7)) * SROW
                          + ((lane >> 3) & 1) * 8) * 2;
    const uint32_t aHiB = sb + aOff;
    const uint32_t aLoB = sb + GA_B + aOff;
    const uint32_t bHiB = sb + 2 * GA_B + bOff;
    const uint32_t bLoB = sb + 2 * GA_B + GB_B + bOff;

    const int nch = Kd / 32;

    {
        #pragma unroll
        for (int c = 0; c < 4; c++) CP16(sA + c * 16, gA + c * 16);
        #pragma unroll
        for (int c = 0; c < 4; c++) {
            CP16(sB + c * 16,      gB + c * 16);
            CP16(sB + 80 + c * 16, gB + (size_t)Kd * 2 + c * 16);
        }
        CP_COMMIT();
    }

    for (int ch = 0; ch < nch; ch++) {
        if (ch + 1 < nch) {
            const uint32_t sw = (uint32_t)((ch + 1) % 3) * G_STGB;
            const int gb = (ch + 1) * 64;
            #pragma unroll
            for (int c = 0; c < 4; c++) CP16(sA + sw + c * 16, gA + gb + c * 16);
            #pragma unroll
            for (int c = 0; c < 4; c++) {
                CP16(sB + sw + c * 16,      gB + gb + c * 16);
                CP16(sB + sw + 80 + c * 16, gB + (size_t)Kd * 2 + gb + c * 16);
            }
            CP_COMMIT();
            CP_WAIT1();
        } else {
            CP_WAIT0();
        }
        __syncthreads();

        const uint32_t so = (uint32_t)(ch % 3) * G_STGB;
        #pragma unroll
        for (int ks = 0; ks < 2; ks++) {
            uint32_t ah[4][4], al[4][4], bh[8][2], bl[8][2];
            #pragma unroll
            for (int mt = 0; mt < 4; mt++) {
                const uint32_t ad = (uint32_t)(mt * 16 * SROW + ks * 16) * 2 + so;
                LDSM4(ah[mt], aHiB + ad);
                LDSM4(al[mt], aLoB + ad);
            }
            #pragma unroll
            for (int p4 = 0; p4 < 4; p4++) {
                const uint32_t bd = (uint32_t)(p4 * 16 * SROW + ks * 16) * 2 + so;
                uint32_t r[4];
                LDSM4(r, bHiB + bd);
                bh[2*p4][0] = r[0]; bh[2*p4][1] = r[1];
                bh[2*p4+1][0] = r[2]; bh[2*p4+1][1] = r[3];
                LDSM4(r, bLoB + bd);
                bl[2*p4][0] = r[0]; bl[2*p4][1] = r[1];
                bl[2*p4+1][0] = r[2]; bl[2*p4+1][1] = r[3];
            }
            #pragma unroll
            for (int mt = 0; mt < 4; mt++)
                #pragma unroll
                for (int nt = 0; nt < 8; nt++) {
                    MMA_BF16(acc[mt][nt], ah[mt], bh[nt]);
                    MMA_BF16(acc[mt][nt], al[mt], bh[nt]);
                    MMA_BF16(acc[mt][nt], ah[mt], bl[nt]);
                }
        }
    }

    const int gid = lane >> 2, tig = lane & 3;
    const int row0 = bm * 128 + wm * 64;
    const int col0 = bn * 256 + wn * 64;
    #pragma unroll
    for (int mt = 0; mt < 4; mt++)
        #pragma unroll
        for (int nt = 0; nt < 8; nt++) {
            const int r  = row0 + mt * 16 + gid;
            const int cc = col0 + nt * 8 + tig * 2;
            const float2 bz = *(const float2*)(bias + cc);
            float2 o0, o1;
            o0.x = acc[mt][nt][0] + bz.x; o0.y = acc[mt][nt][1] + bz.y;
            o1.x = acc[mt][nt][2] + bz.x; o1.y = acc[mt][nt][3] + bz.y;
            *(float2*)(C + (size_t)r * Nd + cc)       = o0;
            *(float2*)(C + (size_t)(r + 8) * Nd + cc) = o1;
        }
}

// ===========================================================================
// MMA flash attention. 256-thread CTA = 256 q-rows x 1 head, 8 warps x
// 32 q-rows. 3-stage cp.async on pre-split K/V planes.
// SEQUENTIAL m-tiles: each m-tile runs S -> softmax -> PV to completion
// before the next, halving live S/P registers (spill elimination).
// K/V fragments are re-loaded per m-tile (L1 has headroom).
// ===========================================================================
#define NKROW 36
#define ARRU  (64 * NKROW)
#define STAGE_U32 (4 * ARRU)
#define STAGE_BYTES (STAGE_U32 * 4)
#define ATTN_DSMEM (3 * STAGE_BYTES)
#define QSCALE 11.541560327111707f

__global__ __launch_bounds__(256, 1)
void attn_mma(const float* __restrict__ qkv)
{
    extern __shared__ __align__(16) uint32_t dsm[];

    const int tid  = threadIdx.x;
    const int lane = tid & 31;
    const int w    = tid >> 5;
    const int g    = lane >> 2;
    const int tig  = lane & 3;
    const int m0   = blockIdx.x * 256;
    const int h    = blockIdx.y;
    const int b    = blockIdx.z;

    const float* base = qkv + (size_t)b * T_SEQ * (3*C_DIM) + h * H_DIM;
    const uint32_t sb = smem_u32(dsm);

    const int pp = tid >> 6;
    const int rr = tid & 63;
    const __nv_bfloat16* kvpl = (pp == 0) ? g_khi : (pp == 1) ? g_klo
                               : (pp == 2) ? g_vhi : g_vlo;
    const char* gsrc0 = (const char*)(kvpl + ((size_t)(b * N_HEADS + h) * T_SEQ + rr) * H_DIM);
    const uint32_t sdst0 = sb + (uint32_t)pp * ARRU * 4 + (uint32_t)rr * 144;

    {
        #pragma unroll
        for (int c = 0; c < 8; c++) CP16(sdst0 + c * 16, gsrc0 + c * 16);
        CP_COMMIT();
    }
    {
        const int r = tid;
        const float* qrow = base + (size_t)(m0 + r) * (3*C_DIM);
        uint32_t* dhi = dsm + STAGE_U32 + r * NKROW;
        uint32_t* dlo = dsm + 2 * STAGE_U32 + r * NKROW;
        #pragma unroll
        for (int i = 0; i < 16; i++) {
            float4 v = *(const float4*)(qrow + i * 4);
            uint32_t h0, l0, h1, l1;
            split2(v.x * QSCALE, v.y * QSCALE, h0, l0);
            split2(v.z * QSCALE, v.w * QSCALE, h1, l1);
            dhi[i*2] = h0; dhi[i*2+1] = h1;
            dlo[i*2] = l0; dlo[i*2+1] = l1;
        }
    }
    __syncthreads();

    uint32_t qh[2][4][4], ql[2][4][4];
    const int t = lane >> 3, rl = lane & 7;
    {
        #pragma unroll
        for (int mt2 = 0; mt2 < 2; mt2++)
            #pragma unroll
            for (int ks = 0; ks < 4; ks++) {
                const uint32_t off =
                    ((uint32_t)(w * 32 + mt2 * 16 + (t & 1) * 8 + rl) * NKROW
                     + ks * 8 + (t >> 1) * 4) * 4;
                LDSM4(qh[mt2][ks], sb + STAGE_BYTES + off);
                LDSM4(ql[mt2][ks], sb + 2 * STAGE_BYTES + off);
            }
    }
    __syncthreads();

    float o[2][8][4];
    #pragma unroll
    for (int mt2 = 0; mt2 < 2; mt2++)
        #pragma unroll
        for (int nt = 0; nt < 8; nt++)
            #pragma unroll
            for (int j = 0; j < 4; j++) o[mt2][nt][j] = 0.0f;
    float m_[2][2] = {{-1e30f, -1e30f}, {-1e30f, -1e30f}};
    float l_[2][2] = {{0.0f, 0.0f}, {0.0f, 0.0f}};

    constexpr int NT = T_SEQ / 64;
    for (int kt = 0; kt < NT; kt++) {
        if (kt + 1 < NT) {
            const uint32_t sw = (uint32_t)((kt + 1) % 3) * STAGE_BYTES;
            const char* gs = gsrc0 + (size_t)(kt + 1) * 64 * H_DIM * 2;
            #pragma unroll
            for (int c = 0; c < 8; c++) CP16(sdst0 + sw + c * 16, gs + c * 16);
            CP_COMMIT();
            CP_WAIT1();
        } else {
            CP_WAIT0();
        }
        __syncthreads();

        const uint32_t so = (uint32_t)(kt % 3) * STAGE_BYTES;

        // ================= sequential m-tiles =================
        #pragma unroll
        for (int mt2 = 0; mt2 < 2; mt2++) {
            // ---- S = Q K^T (bf16x3), this m-tile only ----
            float s[8][4];
            #pragma unroll
            for (int nt = 0; nt < 8; nt++)
                #pragma unroll
                for (int j = 0; j < 4; j++) s[nt][j] = 0.0f;

            #pragma unroll
            for (int ks = 0; ks < 4; ks++) {
                #pragma unroll
                for (int kb = 0; kb < 4; kb++) {
                    const uint32_t off = so +
                        ((uint32_t)(kb * 16 + (t >> 1) * 8 + rl) * NKROW + ks * 8 + (t & 1) * 4) * 4;
                    uint32_t rh[4], rlo[4];
                    LDSM4(rh, sb + off);
                    LDSM4(rlo, sb + ARRU * 4 + off);
                    MMA_BF16(s[2*kb],   qh[mt2][ks], rh);
                    MMA_BF16(s[2*kb],   ql[mt2][ks], rh);
                    MMA_BF16(s[2*kb],   qh[mt2][ks], rlo);
                    MMA_BF16(s[2*kb+1], qh[mt2][ks], rh + 2);
                    MMA_BF16(s[2*kb+1], ql[mt2][ks], rh + 2);
                    MMA_BF16(s[2*kb+1], qh[mt2][ks], rlo + 2);
                }
            }

            // ---- online softmax, this m-tile ----
            float rm0 = -1e30f, rm1 = -1e30f;
            #pragma unroll
            for (int nt = 0; nt < 8; nt++) {
                rm0 = fmaxf(rm0, fmaxf(s[nt][0], s[nt][1]));
                rm1 = fmaxf(rm1, fmaxf(s[nt][2], s[nt][3]));
            }
            rm0 = fmaxf(rm0, __shfl_xor_sync(0xffffffffu, rm0, 1));
            rm0 = fmaxf(rm0, __shfl_xor_sync(0xffffffffu, rm0, 2));
            rm1 = fmaxf(rm1, __shfl_xor_sync(0xffffffffu, rm1, 1));
            rm1 = fmaxf(rm1, __shfl_xor_sync(0xffffffffu, rm1, 2));
            const float mn0 = fmaxf(m_[mt2][0], rm0);
            const float mn1 = fmaxf(m_[mt2][1], rm1);
            const float sc0 = exp2_fast(m_[mt2][0] - mn0);
            const float sc1 = exp2_fast(m_[mt2][1] - mn1);
            m_[mt2][0] = mn0; m_[mt2][1] = mn1;

            float rs0 = 0.0f, rs1 = 0.0f;
            #pragma unroll
            for (int nt = 0; nt < 8; nt++) {
                s[nt][0] = exp2_fast(s[nt][0] - mn0);
                s[nt][1] = exp2_fast(s[nt][1] - mn0);
                s[nt][2] = exp2_fast(s[nt][2] - mn1);
                s[nt][3] = exp2_fast(s[nt][3] - mn1);
                rs0 += s[nt][0] + s[nt][1];
                rs1 += s[nt][2] + s[nt][3];
            }
            rs0 += __shfl_xor_sync(0xffffffffu, rs0, 1);
            rs0 += __shfl_xor_sync(0xffffffffu, rs0, 2);
            rs1 += __shfl_xor_sync(0xffffffffu, rs1, 1);
            rs1 += __shfl_xor_sync(0xffffffffu, rs1, 2);
            l_[mt2][0] = l_[mt2][0] * sc0 + rs0;
            l_[mt2][1] = l_[mt2][1] * sc1 + rs1;

            #pragma unroll
            for (int nt = 0; nt < 8; nt++) {
                o[mt2][nt][0] *= sc0; o[mt2][nt][1] *= sc0;
                o[mt2][nt][2] *= sc1; o[mt2][nt][3] *= sc1;
            }

            // ---- O += P V (bf16x3), this m-tile ----
            #pragma unroll
            for (int ks2 = 0; ks2 < 4; ks2++) {
                uint32_t pah[4], pal[4];
                split2(s[2*ks2][0],   s[2*ks2][1],   pah[0], pal[0]);
                split2(s[2*ks2][2],   s[2*ks2][3],   pah[1], pal[1]);
                split2(s[2*ks2+1][0], s[2*ks2+1][1], pah[2], pal[2]);
                split2(s[2*ks2+1][2], s[2*ks2+1][3], pah[3], pal[3]);
                #pragma unroll
                for (int db = 0; db < 4; db++) {
                    const uint32_t off = so +
                        ((uint32_t)(ks2 * 16 + (t & 1) * 8 + rl) * NKROW + db * 8 + (t >> 1) * 4) * 4;
                    uint32_t rvh[4], rvl[4];
                    LDSM4T(rvh, sb + 2 * ARRU * 4 + off);
                    LDSM4T(rvl, sb + 3 * ARRU * 4 + off);
                    MMA_BF16(o[mt2][2*db],   pah, rvh);
                    MMA_BF16(o[mt2][2*db],   pal, rvh);
                    MMA_BF16(o[mt2][2*db],   pah, rvl);
                    MMA_BF16(o[mt2][2*db+1], pah, rvh + 2);
                    MMA_BF16(o[mt2][2*db+1], pal, rvh + 2);
                    MMA_BF16(o[mt2][2*db+1], pah, rvl + 2);
                }
            }
        }
    }

    // ---- epilogue: O / l -> bf16 hi/lo planes for the proj GEMM ----
    #pragma unroll
    for (int mt2 = 0; mt2 < 2; mt2++) {
        const float inv0 = 1.0f / l_[mt2][0];
        const float inv1 = 1.0f / l_[mt2][1];
        const int qrow = m0 + w * 32 + mt2 * 16 + g;
        const size_t off0 = (size_t)(b * T_SEQ + qrow) * C_DIM + h * H_DIM;
        const size_t off1 = off0 + (size_t)8 * C_DIM;
        #pragma unroll
        for (int nt = 0; nt < 8; nt++) {
            uint32_t hh, ll;
            split2(o[mt2][nt][0] * inv0, o[mt2][nt][1] * inv0, hh, ll);
            *(uint32_t*)(g_ahi + off0 + nt * 8 + tig * 2) = hh;
            *(uint32_t*)(g_alo + off0 + nt * 8 + tig * 2) = ll;
            split2(o[mt2][nt][2] * inv1, o[mt2][nt][3] * inv1, hh, ll);
            *(uint32_t*)(g_ahi + off1 + nt * 8 + tig * 2) = hh;
            *(uint32_t*)(g_alo + off1 + nt * 8 + tig * 2) = ll;
        }
    }
}

// ===========================================================================
extern "C" void kernel_launch(void* const* d_in, const int* in_sizes, int n_in,
                              void* d_out, int out_size)
{
    (void)in_sizes; (void)n_in; (void)out_size;
    const float* x      = (const float*)d_in[0];
    const float* qkv_w  = (const float*)d_in[1];
    const float* qkv_b  = (const float*)d_in[2];
    const float* proj_w = (const float*)d_in[3];
    const float* proj_b = (const float*)d_in[4];
    float* out = (float*)d_out;

    float* qkv_ptr;
    cudaGetSymbolAddress((void**)&qkv_ptr, g_qkv);
    __nv_bfloat16 *xhi, *xlo, *wqh, *wql, *wph, *wpl, *ahi, *alo;
    cudaGetSymbolAddress((void**)&xhi, g_xhi);
    cudaGetSymbolAddress((void**)&xlo, g_xlo);
    cudaGetSymbolAddress((void**)&wqh, g_wqh);
    cudaGetSymbolAddress((void**)&wql, g_wql);
    cudaGetSymbolAddress((void**)&wph, g_wph);
    cudaGetSymbolAddress((void**)&wpl, g_wpl);
    cudaGetSymbolAddress((void**)&ahi, g_ahi);
    cudaGetSymbolAddress((void**)&alo, g_alo);

    cudaFuncSetAttribute(gemm_planes, cudaFuncAttributeMaxDynamicSharedMemorySize, GEMM_DSMEM);
    cudaFuncSetAttribute(attn_mma, cudaFuncAttributeMaxDynamicSharedMemorySize, ATTN_DSMEM);

    // 0) ONE fused prep kernel: split x, qkv_w, proj_w into bf16 hi/lo planes
    split_all_kernel<<<(N4_TOTAL + 255) / 256, 256>>>(
        (const float4*)x, (const float4*)qkv_w, (const float4*)proj_w);

    // 1) QKV GEMM: planes -> g_qkv (f32)
    gemm_planes<<<dim3(3*C_DIM/256, M_ROWS/128), 256, GEMM_DSMEM>>>(
        xhi, xlo, wqh, wql, qkv_b, qkv_ptr, 3*C_DIM, C_DIM);

    // 2) split K/V once into per-(b,h) bf16 planes
    {
        const int n4 = N_BATCH * T_SEQ * C_DIM / 4;
        split_kv_kernel<<<(n4 + 255) / 256, 256>>>(qkv_ptr);
    }

    // 3) MMA flash attention (sequential m-tiles, reduced registers)
    attn_mma<<<dim3(T_SEQ/256, N_HEADS, N_BATCH), 256, ATTN_DSMEM>>>(qkv_ptr);

    // 4) proj GEMM: planes -> out (f32)
    gemm_planes<<<dim3(C_DIM/256, M_ROWS/128), 256, GEMM_DSMEM>>>(
        ahi, alo, wph, wpl, proj_b, out, C_DIM, C_DIM);
}